// round 7
// baseline (speedup 1.0000x reference)
#include <cuda_runtime.h>
#include <cuda_fp16.h>
#include <cstdint>

#define BB   32
#define NN   1024
#define HH   1024
#define NHD  16
#define DD   64
#define BH   (BB*NHD)     // 512
#define MROWS (BB*NN)     // 32768

// -------- scratch (device globals) --------
__device__ float  g_q[BH * NN * DD];
__device__ float  g_k[BH * NN * DD];
__device__ float  g_v[BH * NN * DD];
__device__ float  g_part[4][BH * DD * DD];   // scores partials
__device__ float  g_attn[BH * DD * DD];
__device__ __half g_xh[3][MROWS * HH];
__device__ __half g_wh[4][HH * HH];
__device__ __half g_ch[MROWS * HH];

// ============================================================
// fp32 -> fp16 convert
// ============================================================
struct alignas(16) H8 { __half2 a, b, c, d; };

__global__ void cvt_f32_f16(const float* __restrict__ in,
                            __half* __restrict__ out, int n)
{
    int idx = (blockIdx.x * blockDim.x + threadIdx.x) * 8;
    if (idx >= n) return;
    float4 a = *reinterpret_cast<const float4*>(in + idx);
    float4 b = *reinterpret_cast<const float4*>(in + idx + 4);
    H8 o;
    o.a = __floats2half2_rn(a.x, a.y);
    o.b = __floats2half2_rn(a.z, a.w);
    o.c = __floats2half2_rn(b.x, b.y);
    o.d = __floats2half2_rn(b.z, b.w);
    *reinterpret_cast<H8*>(out + idx) = o;
}

// ============================================================
// mma.sync helpers
// ============================================================
__device__ __forceinline__ uint32_t smem_u32(const void* p) {
    return (uint32_t)__cvta_generic_to_shared(p);
}
__device__ __forceinline__ void cp16(uint32_t dst, const void* src) {
    asm volatile("cp.async.cg.shared.global [%0], [%1], 16;\n" :: "r"(dst), "l"(src));
}
__device__ __forceinline__ void cp_commit() {
    asm volatile("cp.async.commit_group;\n");
}
template<int N> __device__ __forceinline__ void cp_wait() {
    asm volatile("cp.async.wait_group %0;\n" :: "n"(N));
}
__device__ __forceinline__ void ldsm_x4(uint32_t* r, uint32_t addr) {
    asm volatile("ldmatrix.sync.aligned.m8n8.x4.shared.b16 {%0,%1,%2,%3}, [%4];\n"
                 : "=r"(r[0]), "=r"(r[1]), "=r"(r[2]), "=r"(r[3]) : "r"(addr));
}
__device__ __forceinline__ void mma16816(float* c, const uint32_t* a, const uint32_t* b) {
    asm volatile("mma.sync.aligned.m16n8k16.row.col.f32.f16.f16.f32 "
                 "{%0,%1,%2,%3}, {%4,%5,%6,%7}, {%8,%9}, {%0,%1,%2,%3};\n"
                 : "+f"(c[0]), "+f"(c[1]), "+f"(c[2]), "+f"(c[3])
                 : "r"(a[0]), "r"(a[1]), "r"(a[2]), "r"(a[3]),
                   "r"(b[0]), "r"(b[1]));
}

// ============================================================
// HMMA GEMM NT: C[m,h] = sum_k A[m,k]*W[h,k]  (fp16 in, fp32 acc/out)
// CTA 128x128, 8 warps (2m x 4n), warp tile 64x32, K-tile 32, 4 stages.
// 256 threads, OCCUPANCY 2 (two CTAs/SM hide each other's bubbles).
// MODE 0: row-major C   MODE 1: head-split scatter
// ============================================================
#define BM 128
#define BN 128
#define BKH 32
#define LDSS 40                           // halfs; 80B padded rows
#define NITER (HH / BKH)                  // 32
#define NSTG 4
#define STG_A (BM * LDSS * 2)             // 10240 B
#define STG_B (BN * LDSS * 2)             // 10240 B
#define STG   (STG_A + STG_B)             // 20480 B
#define GSMEM (NSTG * STG)                // 81920 B

template<int MODE>
__global__ void __launch_bounds__(256, 2)
hgemm_nt(const __half* __restrict__ A, const __half* __restrict__ W,
         float* __restrict__ C)
{
    extern __shared__ __align__(16) char dynsm[];
    const uint32_t dbase = smem_u32(dynsm);

    const int tid  = threadIdx.x;
    const int lane = tid & 31;
    const int wid  = tid >> 5;
    const int bm = blockIdx.y * BM;
    const int bn = blockIdx.x * BN;

    // ---- loader: row = tid>>1, segment = (tid&1)*16 halfs; 2 cp16 per tile ----
    const int lrow = tid >> 1;             // 0..127
    const int lcol = (tid & 1) * 16;       // halfs: 0 or 16
    const __half* gA = A + (size_t)(bm + lrow) * HH + lcol;
    const __half* gB = W + (size_t)(bn + lrow) * HH + lcol;
    const uint32_t sAoff = (uint32_t)(lrow * LDSS + lcol) * 2;
    const uint32_t sBoff = (uint32_t)STG_A + sAoff;

    auto issue = [&](int it, int buf) {
        const uint32_t sb = dbase + (uint32_t)buf * STG;
        const size_t kofs = (size_t)it * BKH;
        cp16(sb + sAoff,       gA + kofs);
        cp16(sb + sAoff + 16,  gA + kofs + 8);
        cp16(sb + sBoff,       gB + kofs);
        cp16(sb + sBoff + 16,  gB + kofs + 8);
        cp_commit();
    };

    // ---- warp tiling: 2 warps m (64 each), 4 warps n (32 each) ----
    const int wm = (wid & 1) * 64;
    const int wn = (wid >> 1) * 32;
    const int lr = lane & 7;
    const int lt = lane >> 3;
    const int arow_f = wm + (lt & 1) * 8 + lr;
    const int akg    = lt >> 1;
    const int brow_f = wn + (lt >> 1) * 8 + lr;
    const int bkg    = lt & 1;

    float acc[4][4][4];
#pragma unroll
    for (int i = 0; i < 4; i++)
#pragma unroll
        for (int j = 0; j < 4; j++)
#pragma unroll
            for (int r = 0; r < 4; r++) acc[i][j][r] = 0.f;

    issue(0, 0);
    issue(1, 1);
    issue(2, 2);

    for (int it = 0; it < NITER; ++it) {
        const int rem = NITER - 1 - it;
        if (rem >= 2)      cp_wait<2>();
        else if (rem == 1) cp_wait<1>();
        else               cp_wait<0>();
        __syncthreads();

        if (it + 3 < NITER) issue(it + 3, (it + 3) & (NSTG - 1));

        const uint32_t sb = dbase + (uint32_t)(it & (NSTG - 1)) * STG;

#pragma unroll
        for (int s = 0; s < 2; ++s) {
            uint32_t af[4][4];
#pragma unroll
            for (int mi = 0; mi < 4; ++mi)
                ldsm_x4(af[mi], sb +
                    (uint32_t)(((arow_f + mi * 16) * LDSS + (s * 2 + akg) * 8) * 2));
            uint32_t bf[2][4];
#pragma unroll
            for (int p = 0; p < 2; ++p)
                ldsm_x4(bf[p], sb + STG_A +
                    (uint32_t)(((brow_f + p * 16) * LDSS + (s * 2 + bkg) * 8) * 2));
#pragma unroll
            for (int mi = 0; mi < 4; ++mi)
#pragma unroll
                for (int ni = 0; ni < 4; ++ni)
                    mma16816(acc[mi][ni], af[mi], &bf[ni >> 1][(ni & 1) * 2]);
        }
    }

    // ---- epilogue ----
#pragma unroll
    for (int mi = 0; mi < 4; ++mi) {
#pragma unroll
        for (int ni = 0; ni < 4; ++ni) {
            const int m0 = bm + wm + mi * 16 + (lane >> 2);
            const int n0 = bn + wn + ni * 8 + (lane & 3) * 2;
#pragma unroll
            for (int h = 0; h < 2; ++h) {
                const int m = m0 + h * 8;
                const float c0 = acc[mi][ni][h * 2 + 0];
                const float c1 = acc[mi][ni][h * 2 + 1];
                if (MODE == 0) {
                    *reinterpret_cast<float2*>(&C[(size_t)m * HH + n0]) =
                        make_float2(c0, c1);
                } else {
                    const int b  = m >> 10;
                    const int n  = m & 1023;
                    const int nh = n0 >> 6;
                    const int d  = n0 & 63;
                    *reinterpret_cast<float2*>(
                        &C[((size_t)(b * NHD + nh) * NN + n) * DD + d]) =
                        make_float2(c0, c1);
                }
            }
        }
    }
}

// ============================================================
// Scores partials: part[s][b,d,e] = sum_{n in slice s} q[b,n,d]*(k[b,n,e]+pe[n,e])
// ============================================================
__global__ void scores_part_kernel(const float* __restrict__ q,
                                   const float* __restrict__ k,
                                   const float* __restrict__ pe,
                                   float* __restrict__ part)
{
    const int s = blockIdx.x;
    const int b = blockIdx.y;
    const float* qb = q + (size_t)b * NN * DD;
    const float* kb = k + (size_t)b * NN * DD;
    const int nbase = s * 256;

    __shared__ float qs[16][65];
    __shared__ float ks[16][65];

    const int tid = threadIdx.x;
    const int tx = tid & 15;
    const int ty = tid >> 4;
    const int lr = tid >> 4;
    const int lc = (tid & 15) * 4;

    float acc[4][4];
#pragma unroll
    for (int i = 0; i < 4; i++)
#pragma unroll
        for (int j = 0; j < 4; j++) acc[i][j] = 0.f;

    for (int n0 = nbase; n0 < nbase + 256; n0 += 16) {
        float4 q4 = *reinterpret_cast<const float4*>(&qb[(size_t)(n0 + lr) * DD + lc]);
        qs[lr][lc + 0] = q4.x; qs[lr][lc + 1] = q4.y;
        qs[lr][lc + 2] = q4.z; qs[lr][lc + 3] = q4.w;

        float4 k4 = *reinterpret_cast<const float4*>(&kb[(size_t)(n0 + lr) * DD + lc]);
        float4 p4 = *reinterpret_cast<const float4*>(&pe[(size_t)(n0 + lr) * DD + lc]);
        ks[lr][lc + 0] = k4.x + p4.x; ks[lr][lc + 1] = k4.y + p4.y;
        ks[lr][lc + 2] = k4.z + p4.z; ks[lr][lc + 3] = k4.w + p4.w;

        __syncthreads();

#pragma unroll
        for (int kk = 0; kk < 16; kk++) {
            float af[4], bf[4];
#pragma unroll
            for (int i = 0; i < 4; i++) af[i] = qs[kk][ty * 4 + i];
#pragma unroll
            for (int j = 0; j < 4; j++) bf[j] = ks[kk][tx * 4 + j];
#pragma unroll
            for (int i = 0; i < 4; i++)
#pragma unroll
                for (int j = 0; j < 4; j++)
                    acc[i][j] += af[i] * bf[j];
        }
        __syncthreads();
    }

    float* out = part + ((size_t)s * BH + b) * DD * DD;
#pragma unroll
    for (int i = 0; i < 4; i++) {
        const int d = ty * 4 + i;
#pragma unroll
        for (int j = 0; j < 4; j++) {
            const int e = tx * 4 + j;
            out[d * DD + e] = acc[i][j];
        }
    }
}

// ============================================================
// Sum partials + scale + softmax over last axis (64)
// ============================================================
__global__ void softmax64_kernel(const float* __restrict__ part,
                                 float* __restrict__ attn)
{
    const int row  = blockIdx.x * 4 + (threadIdx.x >> 5);   // b*64+d
    const int lane = threadIdx.x & 31;
    const size_t stride = (size_t)BH * DD * DD;
    const size_t base = (size_t)row * 64;

    float v0 = 0.f, v1 = 0.f;
#pragma unroll
    for (int s = 0; s < 4; ++s) {
        v0 += part[s * stride + base + lane];
        v1 += part[s * stride + base + lane + 32];
    }
    v0 *= 0.125f; v1 *= 0.125f;

    float m = fmaxf(v0, v1);
#pragma unroll
    for (int off = 16; off > 0; off >>= 1)
        m = fmaxf(m, __shfl_xor_sync(0xFFFFFFFFu, m, off));
    float e0 = __expf(v0 - m);
    float e1 = __expf(v1 - m);
    float sum = e0 + e1;
#pragma unroll
    for (int off = 16; off > 0; off >>= 1)
        sum += __shfl_xor_sync(0xFFFFFFFFu, sum, off);
    const float inv = 1.0f / sum;
    attn[base + lane]      = e0 * inv;
    attn[base + lane + 32] = e1 * inv;
}

// ============================================================
// AV: ctx_h[bb, n, nh*64+d] = sum_e attn[b,d,e]*v[b,n,e]  (fp16 out)
// ============================================================
__global__ void av_kernel(const float* __restrict__ attn,
                          const float* __restrict__ v,
                          __half* __restrict__ ch)
{
    const int b  = blockIdx.y;
    const int n0 = blockIdx.x * 64;
    const float* ab = attn + (size_t)b * DD * DD;
    const float* vb = v + (size_t)b * NN * DD;

    __shared__ float as[64][65];
    __shared__ float vs[64][65];

    const int tid = threadIdx.x;
    for (int i = tid; i < 64 * 64; i += 256)
        as[i >> 6][i & 63] = ab[i];

    {
        const int lr = tid >> 2;            // 0..63
        const int lc = (tid & 3) * 16;      // 0,16,32,48
#pragma unroll
        for (int u = 0; u < 4; ++u) {
            float4 v4 = *reinterpret_cast<const float4*>(
                &vb[(size_t)(n0 + lr) * DD + lc + u * 4]);
            vs[lr][lc + u * 4 + 0] = v4.x; vs[lr][lc + u * 4 + 1] = v4.y;
            vs[lr][lc + u * 4 + 2] = v4.z; vs[lr][lc + u * 4 + 3] = v4.w;
        }
    }
    __syncthreads();

    const int d = tid & 63;
    const int g = tid >> 6;   // 0..3

    float acc[16];
#pragma unroll
    for (int i = 0; i < 16; i++) acc[i] = 0.f;

#pragma unroll 8
    for (int e = 0; e < 64; e++) {
        const float a = as[d][e];
#pragma unroll
        for (int i = 0; i < 16; i++)
            acc[i] += a * vs[g + 4 * i][e];
    }

    const int bb = b >> 4;
    const int nh = b & 15;
#pragma unroll
    for (int i = 0; i < 16; i++) {
        const int n = n0 + g + 4 * i;
        ch[((size_t)bb * NN + n) * HH + nh * DD + d] = __float2half_rn(acc[i]);
    }
}

// ============================================================
// launch  (GEMMs at call positions 3, 6, 9 for ncu -s 5 -c 1 robustness)
// ============================================================
extern "C" void kernel_launch(void* const* d_in, const int* in_sizes, int n_in,
                              void* d_out, int out_size)
{
    const float* query  = (const float*)d_in[0];
    const float* key    = (const float*)d_in[1];
    const float* value  = (const float*)d_in[2];
    const float* key_pe = (const float*)d_in[3];
    const float* Wq     = (const float*)d_in[4];
    const float* Wk     = (const float*)d_in[5];
    const float* Wv     = (const float*)d_in[6];
    const float* Wo     = (const float*)d_in[7];
    float* out = (float*)d_out;

    float *q, *k, *v, *attn, *part;
    __half *xh, *wh, *ch;
    cudaGetSymbolAddress((void**)&q,    g_q);
    cudaGetSymbolAddress((void**)&k,    g_k);
    cudaGetSymbolAddress((void**)&v,    g_v);
    cudaGetSymbolAddress((void**)&attn, g_attn);
    cudaGetSymbolAddress((void**)&part, g_part);
    cudaGetSymbolAddress((void**)&xh,   g_xh);
    cudaGetSymbolAddress((void**)&wh,   g_wh);
    cudaGetSymbolAddress((void**)&ch,   g_ch);

    static bool attr_done = false;
    if (!attr_done) {
        cudaFuncSetAttribute(hgemm_nt<0>, cudaFuncAttributeMaxDynamicSharedMemorySize, GSMEM);
        cudaFuncSetAttribute(hgemm_nt<1>, cudaFuncAttributeMaxDynamicSharedMemorySize, GSMEM);
        attr_done = true;
    }

    const int nX = MROWS * HH;
    const int nW = HH * HH;

    dim3 gg(HH / BN, MROWS / BM);   // (8, 256) = 2048 CTAs

    cvt_f32_f16<<<nX / 2048, 256>>>(query, xh + 0 * (size_t)nX, nX);                 // 1
    cvt_f32_f16<<<nW / 2048, 256>>>(Wq, wh + 0 * (size_t)nW, nW);                    // 2
    hgemm_nt<1><<<gg, 256, GSMEM>>>(xh + 0 * (size_t)nX, wh + 0 * (size_t)nW, q);    // 3

    cvt_f32_f16<<<nX / 2048, 256>>>(key, xh + 1 * (size_t)nX, nX);                   // 4
    cvt_f32_f16<<<nW / 2048, 256>>>(Wk, wh + 1 * (size_t)nW, nW);                    // 5
    hgemm_nt<1><<<gg, 256, GSMEM>>>(xh + 1 * (size_t)nX, wh + 1 * (size_t)nW, k);    // 6

    cvt_f32_f16<<<nX / 2048, 256>>>(value, xh + 2 * (size_t)nX, nX);                 // 7
    cvt_f32_f16<<<nW / 2048, 256>>>(Wv, wh + 2 * (size_t)nW, nW);                    // 8
    hgemm_nt<1><<<gg, 256, GSMEM>>>(xh + 2 * (size_t)nX, wh + 2 * (size_t)nW, v);    // 9

    cvt_f32_f16<<<nW / 2048, 256>>>(Wo, wh + 3 * (size_t)nW, nW);                    // 10

    scores_part_kernel<<<dim3(4, BH), 256>>>(q, k, key_pe, part);                    // 11
    softmax64_kernel<<<(BH * DD) / 4, 128>>>(part, attn);                            // 12
    av_kernel<<<dim3(NN / 64, BH), 256>>>(attn, v, ch);                              // 13

    hgemm_nt<0><<<gg, 256, GSMEM>>>(ch, wh + 3 * (size_t)nW, out);                   // 14
}